// round 1
// baseline (speedup 1.0000x reference)
#include <cuda_runtime.h>

#define B_N 8
#define T_N 4096
#define CH  256
#define NL  8
#define TT  128
#define KC  32
#define BSW 384   // extended Bs row width for the dilated-conv kernel

// ---- scratch (device globals; no allocations allowed) ----
__device__ float g_x[B_N * CH * T_N];        // 32 MB
__device__ float g_acts[B_N * CH * T_N];     // 32 MB
__device__ float g_outacc[B_N * CH * T_N];   // 32 MB
__device__ float g_inw_t[NL * 3 * CH * 512]; // [layer][k][c][o]  (o contiguous)
__device__ float g_rsw_t[NL * CH * 512];     // [layer][c][o]
__device__ float g_condw_t[NL * 80 * 512];   // [layer][m][o]

// ---------------- weight transposes (coalesced-dst layouts) ----------------
__global__ void tr_inw_kernel(const float* __restrict__ w) {
    int idx = blockIdx.x * 256 + threadIdx.x;
    if (idx >= NL * 512 * CH * 3) return;
    int k = idx % 3;
    int c = (idx / 3) % CH;
    int o = (idx / (3 * CH)) % 512;
    int i = idx / (3 * CH * 512);
    g_inw_t[((i * 3 + k) * CH + c) * 512 + o] = w[idx];
}

__global__ void tr_rsw_kernel(const float* __restrict__ w) {
    int idx = blockIdx.x * 256 + threadIdx.x;
    if (idx >= NL * 512 * CH) return;
    int c = idx & (CH - 1);
    int o = (idx >> 8) & 511;
    int i = idx >> 17;
    g_rsw_t[(i * CH + c) * 512 + o] = w[idx];
}

__global__ void tr_cw_kernel(const float* __restrict__ w) {
    int idx = blockIdx.x * 256 + threadIdx.x;
    if (idx >= NL * 512 * 80) return;
    int m = idx % 80;
    int og = idx / 80;           // global out channel 0..4095
    int i = og >> 9;
    int o = og & 511;
    g_condw_t[(i * 80 + m) * 512 + o] = w[idx];
}

// ---------------- start conv (1x1, 4->256) + zero out_acc ----------------
__global__ void start_kernel(const float* __restrict__ f,
                             const float* __restrict__ sw,
                             const float* __restrict__ sb) {
    int idx = blockIdx.x * 256 + threadIdx.x;   // over B*CH*T
    int t = idx & (T_N - 1);
    int c = (idx >> 12) & (CH - 1);
    int b = idx >> 20;
    const float* fb = f + (size_t)b * 8 * T_N;  // f0 = first 4 channels
    float acc = sb[c];
#pragma unroll
    for (int i = 0; i < 4; i++)
        acc = fmaf(fb[(size_t)i * T_N + t], sw[c * 4 + i], acc);
    g_x[idx] = acc;
    g_outacc[idx] = 0.f;
}

// ---------------- main dilated conv + cond conv + gate ----------------
// Block: (t-tile 128) x (64 j-pairs = 128 out rows) for one batch.
// Thread (ty,tx): rows {j0+ty*4+i} (tanh half) and {j0+256+ty*4+i} (sigmoid half),
// cols t0 + tx + 16u, u<8.  Epilogue writes acts = tanh(a1)*sigmoid(a2).
extern __shared__ float smem_dyn[];
__global__ __launch_bounds__(256) void layer_conv_kernel(
    const float* __restrict__ context,
    const float* __restrict__ in_b,
    const float* __restrict__ cond_b,
    int li, int d) {
    float* As = smem_dyn;                 // [3][KC][128]
    float* Bs = smem_dyn + 3 * KC * 128;  // [KC][BSW]

    int tid = threadIdx.x;
    int tx = tid & 15;
    int ty = tid >> 4;
    int t0 = blockIdx.x * TT;
    int j0 = blockIdx.y * 64;
    int b  = blockIdx.z;

    const float* xb = g_x + (size_t)b * CH * T_N;
    const float* wt = g_inw_t + (size_t)li * 3 * CH * 512;

    float acc[8][8];
#pragma unroll
    for (int i = 0; i < 8; i++)
#pragma unroll
        for (int u = 0; u < 8; u++) acc[i][u] = 0.f;

    // ===== x part: 3 dilated taps share one extended window per c-chunk =====
    for (int c0 = 0; c0 < CH; c0 += KC) {
        // As: 3*KC*128 floats -> 3072 float4, 12 per thread
#pragma unroll
        for (int e = 0; e < 12; e++) {
            int v = e * 256 + tid;
            int r4 = v & 31;
            int kkk = v >> 5;           // k*KC + kk
            int kk = kkk & (KC - 1);
            int k = kkk >> 5;
            int r = r4 * 4;
            int o = (r < 64) ? (j0 + r) : (256 + j0 + r - 64);
            float4 val = *(const float4*)(wt + ((size_t)(k * CH) + c0 + kk) * 512 + o);
            *(float4*)(As + kkk * 128 + r) = val;
        }
        // Bs: KC rows x 384 cols, window [t0-128, t0+256)
#pragma unroll
        for (int e = 0; e < 12; e++) {
            int v = e * 256 + tid;
            int c4 = v % 96;
            int kk = v / 96;
            int t = t0 - 128 + c4 * 4;
            float4 val = make_float4(0.f, 0.f, 0.f, 0.f);
            if (t >= 0 && t < T_N)
                val = *(const float4*)(xb + (size_t)(c0 + kk) * T_N + t);
            *(float4*)(Bs + kk * BSW + c4 * 4) = val;
        }
        __syncthreads();
#pragma unroll 4
        for (int kk = 0; kk < KC; kk++) {
#pragma unroll
            for (int k = 0; k < 3; k++) {
                const float* ap = As + (k * KC + kk) * 128;
                float4 A0 = *(const float4*)(ap + ty * 4);
                float4 A1 = *(const float4*)(ap + 64 + ty * 4);
                float av[8] = {A0.x, A0.y, A0.z, A0.w, A1.x, A1.y, A1.z, A1.w};
                const float* bp = Bs + kk * BSW + 128 + (k - 1) * d + tx;
#pragma unroll
                for (int u = 0; u < 8; u++) {
                    float bv = bp[u * 16];
#pragma unroll
                    for (int i = 0; i < 8; i++)
                        acc[i][u] = fmaf(av[i], bv, acc[i][u]);
                }
            }
        }
        __syncthreads();
    }

    // ===== context part (1x1, K=80, zero-padded to KC chunks) =====
    const float* cwt = g_condw_t + (size_t)li * 80 * 512;
    const float* ctxb = context + (size_t)b * 80 * T_N;
    for (int m0 = 0; m0 < 80; m0 += KC) {
#pragma unroll
        for (int e = 0; e < 4; e++) {
            int v = e * 256 + tid;
            int r4 = v & 31;
            int kk = v >> 5;
            int r = r4 * 4;
            int o = (r < 64) ? (j0 + r) : (256 + j0 + r - 64);
            float4 val = make_float4(0.f, 0.f, 0.f, 0.f);
            if (m0 + kk < 80)
                val = *(const float4*)(cwt + (size_t)(m0 + kk) * 512 + o);
            *(float4*)(As + kk * 128 + r) = val;
        }
#pragma unroll
        for (int e = 0; e < 4; e++) {
            int v = e * 256 + tid;
            int c4 = v & 31;
            int kk = v >> 5;
            float4 val = make_float4(0.f, 0.f, 0.f, 0.f);
            if (m0 + kk < 80)
                val = *(const float4*)(ctxb + (size_t)(m0 + kk) * T_N + t0 + c4 * 4);
            *(float4*)(Bs + kk * BSW + 128 + c4 * 4) = val;
        }
        __syncthreads();
#pragma unroll 4
        for (int kk = 0; kk < KC; kk++) {
            const float* ap = As + kk * 128;
            float4 A0 = *(const float4*)(ap + ty * 4);
            float4 A1 = *(const float4*)(ap + 64 + ty * 4);
            float av[8] = {A0.x, A0.y, A0.z, A0.w, A1.x, A1.y, A1.z, A1.w};
            const float* bp = Bs + kk * BSW + 128 + tx;
#pragma unroll
            for (int u = 0; u < 8; u++) {
                float bv = bp[u * 16];
#pragma unroll
                for (int i = 0; i < 8; i++)
                    acc[i][u] = fmaf(av[i], bv, acc[i][u]);
            }
        }
        __syncthreads();
    }

    // ===== epilogue: biases + tanh*sigmoid gate =====
    const float* ibl = in_b + li * 512;
    const float* cbl = cond_b + li * 512;
    float* actsb = g_acts + (size_t)b * CH * T_N;
#pragma unroll
    for (int i = 0; i < 4; i++) {
        int jj = j0 + ty * 4 + i;
        float b1 = ibl[jj] + cbl[jj];
        float b2 = ibl[256 + jj] + cbl[256 + jj];
        float* dst = actsb + (size_t)jj * T_N + t0 + tx;
#pragma unroll
        for (int u = 0; u < 8; u++) {
            float a1 = acc[i][u] + b1;
            float a2 = acc[i + 4][u] + b2;
            float s = 1.f / (1.f + __expf(-a2));
            dst[u * 16] = tanhf(a1) * s;
        }
    }
}

// ---------------- res/skip 1x1 conv (256->512) + residual update ----------------
__global__ __launch_bounds__(256) void rs_kernel(const float* __restrict__ rs_b,
                                                 int li, int last) {
    __shared__ float As[KC * 128];
    __shared__ float Bs[KC * 128];

    int tid = threadIdx.x;
    int tx = tid & 15;
    int ty = tid >> 4;
    int t0 = blockIdx.x * TT;
    int j0 = blockIdx.y * 64;
    int b  = blockIdx.z;

    const float* wt = g_rsw_t + (size_t)li * CH * 512;
    const float* actsb = g_acts + (size_t)b * CH * T_N;

    float acc[8][8];
#pragma unroll
    for (int i = 0; i < 8; i++)
#pragma unroll
        for (int u = 0; u < 8; u++) acc[i][u] = 0.f;

    for (int c0 = 0; c0 < CH; c0 += KC) {
#pragma unroll
        for (int e = 0; e < 4; e++) {
            int v = e * 256 + tid;
            int r4 = v & 31;
            int kk = v >> 5;
            int r = r4 * 4;
            int o = (r < 64) ? (j0 + r) : (256 + j0 + r - 64);
            *(float4*)(As + kk * 128 + r) =
                *(const float4*)(wt + (size_t)(c0 + kk) * 512 + o);
        }
#pragma unroll
        for (int e = 0; e < 4; e++) {
            int v = e * 256 + tid;
            int c4 = v & 31;
            int kk = v >> 5;
            *(float4*)(Bs + kk * 128 + c4 * 4) =
                *(const float4*)(actsb + (size_t)(c0 + kk) * T_N + t0 + c4 * 4);
        }
        __syncthreads();
#pragma unroll 4
        for (int kk = 0; kk < KC; kk++) {
            const float* ap = As + kk * 128;
            float4 A0 = *(const float4*)(ap + ty * 4);
            float4 A1 = *(const float4*)(ap + 64 + ty * 4);
            float av[8] = {A0.x, A0.y, A0.z, A0.w, A1.x, A1.y, A1.z, A1.w};
            const float* bp = Bs + kk * 128 + tx;
#pragma unroll
            for (int u = 0; u < 8; u++) {
                float bv = bp[u * 16];
#pragma unroll
                for (int i = 0; i < 8; i++)
                    acc[i][u] = fmaf(av[i], bv, acc[i][u]);
            }
        }
        __syncthreads();
    }

    const float* rbl = rs_b + li * 512;
    size_t base = (size_t)b * CH * T_N;
#pragma unroll
    for (int i = 0; i < 4; i++) {
        int jj = j0 + ty * 4 + i;
        float rb1 = rbl[jj];
        float rb2 = rbl[256 + jj];
        size_t idx0 = base + (size_t)jj * T_N + t0 + tx;
#pragma unroll
        for (int u = 0; u < 8; u++) {
            size_t id = idx0 + (size_t)u * 16;
            float r1 = acc[i][u] + rb1;
            if (!last) {
                g_x[id] += r1;
                g_outacc[id] += acc[i + 4][u] + rb2;
            } else {
                g_outacc[id] += r1;   // last layer: output += rs[:256]
            }
        }
    }
}

// ---------------- end conv (1x1, 256->8) + affine transform ----------------
__global__ void end_kernel(const float* __restrict__ forecast,
                           const float* __restrict__ ew,
                           const float* __restrict__ eb,
                           float* __restrict__ out) {
    __shared__ float w[8 * CH];
    int tid = threadIdx.x;
    for (int e = tid; e < 8 * CH; e += 256) w[e] = ew[e];
    __syncthreads();

    int idx = blockIdx.x * 256 + tid;  // over B*T
    int t = idx & (T_N - 1);
    int b = idx >> 12;

    float acc[8];
#pragma unroll
    for (int o = 0; o < 8; o++) acc[o] = eb[o];
    const float* oa = g_outacc + (size_t)b * CH * T_N + t;
    for (int c = 0; c < CH; c++) {
        float v = oa[(size_t)c * T_N];
#pragma unroll
        for (int o = 0; o < 8; o++)
            acc[o] = fmaf(v, w[o * CH + c], acc[o]);
    }

    const float* fb = forecast + (size_t)b * 8 * T_N + t;
    float* cc = out + (size_t)b * 8 * T_N + t;                       // concat [B,8,T]
    float* lo = out + (size_t)B_N * 8 * T_N + (size_t)b * 4 * T_N + t; // log_s [B,4,T]
#pragma unroll
    for (int l = 0; l < 4; l++) {
        cc[(size_t)l * T_N] = fb[(size_t)l * T_N];                   // f0 passthrough
        float ls = acc[4 + l];                                       // log_s channel
        cc[(size_t)(4 + l) * T_N] =
            expf(ls) * fb[(size_t)(4 + l) * T_N] + acc[l];           // exp(ls)*f1 + b
        lo[(size_t)l * T_N] = ls;
    }
}

// ---------------- launch ----------------
static const int DIL[NL] = {1, 2, 4, 8, 16, 32, 64, 128};

extern "C" void kernel_launch(void* const* d_in, const int* in_sizes, int n_in,
                              void* d_out, int out_size) {
    const float* forecast = (const float*)d_in[0];
    const float* context  = (const float*)d_in[1];
    const float* start_w  = (const float*)d_in[2];
    const float* start_b  = (const float*)d_in[3];
    const float* cond_w   = (const float*)d_in[4];
    const float* cond_b   = (const float*)d_in[5];
    const float* in_w     = (const float*)d_in[6];
    const float* in_b     = (const float*)d_in[7];
    const float* rs_w     = (const float*)d_in[8];
    const float* rs_b     = (const float*)d_in[9];
    const float* end_w    = (const float*)d_in[10];
    const float* end_b    = (const float*)d_in[11];
    float* out = (float*)d_out;
    (void)in_sizes; (void)n_in; (void)out_size;

    int smem_conv = (3 * KC * 128 + KC * BSW) * (int)sizeof(float);  // 96 KB
    cudaFuncSetAttribute(layer_conv_kernel,
                         cudaFuncAttributeMaxDynamicSharedMemorySize, smem_conv);

    tr_inw_kernel<<<(NL * 512 * CH * 3 + 255) / 256, 256>>>(in_w);
    tr_rsw_kernel<<<(NL * 512 * CH + 255) / 256, 256>>>(rs_w);
    tr_cw_kernel<<<(NL * 512 * 80 + 255) / 256, 256>>>(cond_w);

    start_kernel<<<(B_N * CH * T_N) / 256, 256>>>(forecast, start_w, start_b);

    dim3 grid(T_N / TT, CH / 64, B_N);
    for (int li = 0; li < NL; li++) {
        layer_conv_kernel<<<grid, 256, smem_conv>>>(context, in_b, cond_b, li, DIL[li]);
        rs_kernel<<<grid, 256>>>(rs_b, li, li == NL - 1 ? 1 : 0);
    }

    end_kernel<<<(B_N * T_N) / 256, 256>>>(forecast, end_w, end_b, out);
}

// round 2
// speedup vs baseline: 1.1411x; 1.1411x over previous
#include <cuda_runtime.h>

#define B_N 8
#define T_N 4096
#define CH  256
#define NL  8
#define TT  128
#define KC  32
#define BSW 384   // extended Bs row width for the dilated-conv kernel

typedef unsigned long long u64;

// ---- f32x2 packed helpers ----
__device__ __forceinline__ u64 bcast2(float v) {
    u64 r; unsigned int b = __float_as_uint(v);
    asm("mov.b64 %0, {%1, %1};" : "=l"(r) : "r"(b));
    return r;
}
__device__ __forceinline__ void ffma2(u64& acc, u64 a, u64 b) {
    asm("fma.rn.f32x2 %0, %1, %2, %0;" : "+l"(acc) : "l"(a), "l"(b));
}
__device__ __forceinline__ float2 unpack2(u64 v) {
    float2 f;
    asm("mov.b64 {%0, %1}, %2;" : "=f"(f.x), "=f"(f.y) : "l"(v));
    return f;
}

// ---- scratch (device globals; no allocations allowed) ----
__device__ float g_x[B_N * CH * T_N];        // 32 MB
__device__ float g_acts[B_N * CH * T_N];     // 32 MB
__device__ float g_outacc[B_N * CH * T_N];   // 32 MB
__device__ float g_inw_t[NL * 3 * CH * 512]; // [layer][k][c][o]  (o contiguous)
__device__ float g_rsw_t[NL * CH * 512];     // [layer][c][o]
__device__ float g_condw_t[NL * 80 * 512];   // [layer][m][o]

// ---------------- weight transposes (coalesced-dst layouts) ----------------
__global__ void tr_inw_kernel(const float* __restrict__ w) {
    int idx = blockIdx.x * 256 + threadIdx.x;
    if (idx >= NL * 512 * CH * 3) return;
    int k = idx % 3;
    int c = (idx / 3) % CH;
    int o = (idx / (3 * CH)) % 512;
    int i = idx / (3 * CH * 512);
    g_inw_t[((i * 3 + k) * CH + c) * 512 + o] = w[idx];
}

__global__ void tr_rsw_kernel(const float* __restrict__ w) {
    int idx = blockIdx.x * 256 + threadIdx.x;
    if (idx >= NL * 512 * CH) return;
    int c = idx & (CH - 1);
    int o = (idx >> 8) & 511;
    int i = idx >> 17;
    g_rsw_t[(i * CH + c) * 512 + o] = w[idx];
}

__global__ void tr_cw_kernel(const float* __restrict__ w) {
    int idx = blockIdx.x * 256 + threadIdx.x;
    if (idx >= NL * 512 * 80) return;
    int m = idx % 80;
    int og = idx / 80;           // global out channel 0..4095
    int i = og >> 9;
    int o = og & 511;
    g_condw_t[(i * 80 + m) * 512 + o] = w[idx];
}

// ---------------- start conv (1x1, 4->256) + zero out_acc ----------------
__global__ void start_kernel(const float* __restrict__ f,
                             const float* __restrict__ sw,
                             const float* __restrict__ sb) {
    int idx = blockIdx.x * 256 + threadIdx.x;   // over B*CH*T
    int t = idx & (T_N - 1);
    int c = (idx >> 12) & (CH - 1);
    int b = idx >> 20;
    const float* fb = f + (size_t)b * 8 * T_N;  // f0 = first 4 channels
    float acc = sb[c];
#pragma unroll
    for (int i = 0; i < 4; i++)
        acc = fmaf(fb[(size_t)i * T_N + t], sw[c * 4 + i], acc);
    g_x[idx] = acc;
    g_outacc[idx] = 0.f;
}

// ---------------- main dilated conv + cond conv + gate ----------------
// Block: (t-tile 128) x (64 j-pairs = 128 out rows) for one batch.
// Accumulators are f32x2 pairs along the output-row dimension:
//   acc2[0..1][u] = rows j0+ty*4+{0,1},{2,3}         (tanh half)
//   acc2[2..3][u] = rows 256+j0+ty*4+{0,1},{2,3}     (sigmoid half)
// cols t0 + tx + 16u, u<8.
extern __shared__ float smem_dyn[];
__global__ __launch_bounds__(256) void layer_conv_kernel(
    const float* __restrict__ context,
    const float* __restrict__ in_b,
    const float* __restrict__ cond_b,
    int li, int d) {
    float* As = smem_dyn;                 // [3][KC][128]
    float* Bs = smem_dyn + 3 * KC * 128;  // [KC][BSW]

    int tid = threadIdx.x;
    int tx = tid & 15;
    int ty = tid >> 4;
    int t0 = blockIdx.x * TT;
    int j0 = blockIdx.y * 64;
    int b  = blockIdx.z;

    const float* xb = g_x + (size_t)b * CH * T_N;
    const float* wt = g_inw_t + (size_t)li * 3 * CH * 512;

    u64 acc2[4][8];
#pragma unroll
    for (int i = 0; i < 4; i++)
#pragma unroll
        for (int u = 0; u < 8; u++) acc2[i][u] = 0ULL;

    // ===== x part: 3 dilated taps share one extended window per c-chunk =====
    for (int c0 = 0; c0 < CH; c0 += KC) {
        // As: 3*KC*128 floats -> 3072 float4, 12 per thread
#pragma unroll
        for (int e = 0; e < 12; e++) {
            int v = e * 256 + tid;
            int r4 = v & 31;
            int kkk = v >> 5;           // k*KC + kk
            int r = r4 * 4;
            int o = (r < 64) ? (j0 + r) : (256 + j0 + r - 64);
            int kk = kkk & (KC - 1);
            int k = kkk >> 5;
            float4 val = *(const float4*)(wt + ((size_t)(k * CH) + c0 + kk) * 512 + o);
            *(float4*)(As + kkk * 128 + r) = val;
        }
        // Bs: KC rows x 384 cols, window [t0-128, t0+256)
#pragma unroll
        for (int e = 0; e < 12; e++) {
            int v = e * 256 + tid;
            int c4 = v % 96;
            int kk = v / 96;
            int t = t0 - 128 + c4 * 4;
            float4 val = make_float4(0.f, 0.f, 0.f, 0.f);
            if (t >= 0 && t < T_N)
                val = *(const float4*)(xb + (size_t)(c0 + kk) * T_N + t);
            *(float4*)(Bs + kk * BSW + c4 * 4) = val;
        }
        __syncthreads();
#pragma unroll 4
        for (int kk = 0; kk < KC; kk++) {
#pragma unroll
            for (int k = 0; k < 3; k++) {
                const float* ap = As + (k * KC + kk) * 128;
                ulonglong2 A0 = *(const ulonglong2*)(ap + ty * 4);
                ulonglong2 A1 = *(const ulonglong2*)(ap + 64 + ty * 4);
                const float* bp = Bs + kk * BSW + 128 + (k - 1) * d + tx;
#pragma unroll
                for (int u = 0; u < 8; u++) {
                    u64 bv2 = bcast2(bp[u * 16]);
                    ffma2(acc2[0][u], A0.x, bv2);
                    ffma2(acc2[1][u], A0.y, bv2);
                    ffma2(acc2[2][u], A1.x, bv2);
                    ffma2(acc2[3][u], A1.y, bv2);
                }
            }
        }
        __syncthreads();
    }

    // ===== context part (1x1, K=80, zero-padded to KC chunks) =====
    const float* cwt = g_condw_t + (size_t)li * 80 * 512;
    const float* ctxb = context + (size_t)b * 80 * T_N;
    for (int m0 = 0; m0 < 80; m0 += KC) {
#pragma unroll
        for (int e = 0; e < 4; e++) {
            int v = e * 256 + tid;
            int r4 = v & 31;
            int kk = v >> 5;
            int r = r4 * 4;
            int o = (r < 64) ? (j0 + r) : (256 + j0 + r - 64);
            float4 val = make_float4(0.f, 0.f, 0.f, 0.f);
            if (m0 + kk < 80)
                val = *(const float4*)(cwt + (size_t)(m0 + kk) * 512 + o);
            *(float4*)(As + kk * 128 + r) = val;
        }
#pragma unroll
        for (int e = 0; e < 4; e++) {
            int v = e * 256 + tid;
            int c4 = v & 31;
            int kk = v >> 5;
            float4 val = make_float4(0.f, 0.f, 0.f, 0.f);
            if (m0 + kk < 80)
                val = *(const float4*)(ctxb + (size_t)(m0 + kk) * T_N + t0 + c4 * 4);
            *(float4*)(Bs + kk * BSW + 128 + c4 * 4) = val;
        }
        __syncthreads();
#pragma unroll 4
        for (int kk = 0; kk < KC; kk++) {
            const float* ap = As + kk * 128;
            ulonglong2 A0 = *(const ulonglong2*)(ap + ty * 4);
            ulonglong2 A1 = *(const ulonglong2*)(ap + 64 + ty * 4);
            const float* bp = Bs + kk * BSW + 128 + tx;
#pragma unroll
            for (int u = 0; u < 8; u++) {
                u64 bv2 = bcast2(bp[u * 16]);
                ffma2(acc2[0][u], A0.x, bv2);
                ffma2(acc2[1][u], A0.y, bv2);
                ffma2(acc2[2][u], A1.x, bv2);
                ffma2(acc2[3][u], A1.y, bv2);
            }
        }
        __syncthreads();
    }

    // ===== epilogue: biases + tanh*sigmoid gate =====
    const float* ibl = in_b + li * 512;
    const float* cbl = cond_b + li * 512;
    float* actsb = g_acts + (size_t)b * CH * T_N;
#pragma unroll
    for (int i2 = 0; i2 < 2; i2++) {
        int jj = j0 + ty * 4 + 2 * i2;     // row pair jj, jj+1
        float b1a = ibl[jj]       + cbl[jj];
        float b1b = ibl[jj + 1]   + cbl[jj + 1];
        float b2a = ibl[256 + jj]     + cbl[256 + jj];
        float b2b = ibl[256 + jj + 1] + cbl[256 + jj + 1];
        float* dst0 = actsb + (size_t)jj * T_N + t0 + tx;
        float* dst1 = dst0 + T_N;
#pragma unroll
        for (int u = 0; u < 8; u++) {
            float2 a1 = unpack2(acc2[i2][u]);
            float2 a2 = unpack2(acc2[2 + i2][u]);
            float s0 = 1.f / (1.f + __expf(-(a2.x + b2a)));
            float s1 = 1.f / (1.f + __expf(-(a2.y + b2b)));
            dst0[u * 16] = tanhf(a1.x + b1a) * s0;
            dst1[u * 16] = tanhf(a1.y + b1b) * s1;
        }
    }
}

// ---------------- res/skip 1x1 conv (256->512) + residual update ----------------
__global__ __launch_bounds__(256) void rs_kernel(const float* __restrict__ rs_b,
                                                 int li, int last) {
    __shared__ float As[KC * 128];
    __shared__ float Bs[KC * 128];

    int tid = threadIdx.x;
    int tx = tid & 15;
    int ty = tid >> 4;
    int t0 = blockIdx.x * TT;
    int j0 = blockIdx.y * 64;
    int b  = blockIdx.z;

    const float* wt = g_rsw_t + (size_t)li * CH * 512;
    const float* actsb = g_acts + (size_t)b * CH * T_N;

    u64 acc2[4][8];
#pragma unroll
    for (int i = 0; i < 4; i++)
#pragma unroll
        for (int u = 0; u < 8; u++) acc2[i][u] = 0ULL;

    for (int c0 = 0; c0 < CH; c0 += KC) {
#pragma unroll
        for (int e = 0; e < 4; e++) {
            int v = e * 256 + tid;
            int r4 = v & 31;
            int kk = v >> 5;
            int r = r4 * 4;
            int o = (r < 64) ? (j0 + r) : (256 + j0 + r - 64);
            *(float4*)(As + kk * 128 + r) =
                *(const float4*)(wt + (size_t)(c0 + kk) * 512 + o);
        }
#pragma unroll
        for (int e = 0; e < 4; e++) {
            int v = e * 256 + tid;
            int c4 = v & 31;
            int kk = v >> 5;
            *(float4*)(Bs + kk * 128 + c4 * 4) =
                *(const float4*)(actsb + (size_t)(c0 + kk) * T_N + t0 + c4 * 4);
        }
        __syncthreads();
#pragma unroll 4
        for (int kk = 0; kk < KC; kk++) {
            const float* ap = As + kk * 128;
            ulonglong2 A0 = *(const ulonglong2*)(ap + ty * 4);
            ulonglong2 A1 = *(const ulonglong2*)(ap + 64 + ty * 4);
            const float* bp = Bs + kk * 128 + tx;
#pragma unroll
            for (int u = 0; u < 8; u++) {
                u64 bv2 = bcast2(bp[u * 16]);
                ffma2(acc2[0][u], A0.x, bv2);
                ffma2(acc2[1][u], A0.y, bv2);
                ffma2(acc2[2][u], A1.x, bv2);
                ffma2(acc2[3][u], A1.y, bv2);
            }
        }
        __syncthreads();
    }

    const float* rbl = rs_b + li * 512;
    size_t base = (size_t)b * CH * T_N;
#pragma unroll
    for (int i2 = 0; i2 < 2; i2++) {
        int jj = j0 + ty * 4 + 2 * i2;     // row pair jj, jj+1
        float rb1a = rbl[jj];
        float rb1b = rbl[jj + 1];
        float rb2a = rbl[256 + jj];
        float rb2b = rbl[256 + jj + 1];
        size_t idx0 = base + (size_t)jj * T_N + t0 + tx;
        size_t idx1 = idx0 + T_N;
#pragma unroll
        for (int u = 0; u < 8; u++) {
            float2 r1 = unpack2(acc2[i2][u]);
            float2 r2 = unpack2(acc2[2 + i2][u]);
            size_t o = (size_t)u * 16;
            if (!last) {
                g_x[idx0 + o] += r1.x + rb1a;
                g_x[idx1 + o] += r1.y + rb1b;
                g_outacc[idx0 + o] += r2.x + rb2a;
                g_outacc[idx1 + o] += r2.y + rb2b;
            } else {
                g_outacc[idx0 + o] += r1.x + rb1a;   // last layer: output += rs[:256]
                g_outacc[idx1 + o] += r1.y + rb1b;
            }
        }
    }
}

// ---------------- end conv (1x1, 256->8) + affine transform ----------------
__global__ void end_kernel(const float* __restrict__ forecast,
                           const float* __restrict__ ew,
                           const float* __restrict__ eb,
                           float* __restrict__ out) {
    __shared__ float w[8 * CH];
    int tid = threadIdx.x;
    for (int e = tid; e < 8 * CH; e += 256) w[e] = ew[e];
    __syncthreads();

    int idx = blockIdx.x * 256 + tid;  // over B*T
    int t = idx & (T_N - 1);
    int b = idx >> 12;

    float acc[8];
#pragma unroll
    for (int o = 0; o < 8; o++) acc[o] = eb[o];
    const float* oa = g_outacc + (size_t)b * CH * T_N + t;
    for (int c = 0; c < CH; c++) {
        float v = oa[(size_t)c * T_N];
#pragma unroll
        for (int o = 0; o < 8; o++)
            acc[o] = fmaf(v, w[o * CH + c], acc[o]);
    }

    const float* fb = forecast + (size_t)b * 8 * T_N + t;
    float* cc = out + (size_t)b * 8 * T_N + t;                       // concat [B,8,T]
    float* lo = out + (size_t)B_N * 8 * T_N + (size_t)b * 4 * T_N + t; // log_s [B,4,T]
#pragma unroll
    for (int l = 0; l < 4; l++) {
        cc[(size_t)l * T_N] = fb[(size_t)l * T_N];                   // f0 passthrough
        float ls = acc[4 + l];                                       // log_s channel
        cc[(size_t)(4 + l) * T_N] =
            expf(ls) * fb[(size_t)(4 + l) * T_N] + acc[l];           // exp(ls)*f1 + b
        lo[(size_t)l * T_N] = ls;
    }
}

// ---------------- launch ----------------
static const int DIL[NL] = {1, 2, 4, 8, 16, 32, 64, 128};

extern "C" void kernel_launch(void* const* d_in, const int* in_sizes, int n_in,
                              void* d_out, int out_size) {
    const float* forecast = (const float*)d_in[0];
    const float* context  = (const float*)d_in[1];
    const float* start_w  = (const float*)d_in[2];
    const float* start_b  = (const float*)d_in[3];
    const float* cond_w   = (const float*)d_in[4];
    const float* cond_b   = (const float*)d_in[5];
    const float* in_w     = (const float*)d_in[6];
    const float* in_b     = (const float*)d_in[7];
    const float* rs_w     = (const float*)d_in[8];
    const float* rs_b     = (const float*)d_in[9];
    const float* end_w    = (const float*)d_in[10];
    const float* end_b    = (const float*)d_in[11];
    float* out = (float*)d_out;
    (void)in_sizes; (void)n_in; (void)out_size;

    int smem_conv = (3 * KC * 128 + KC * BSW) * (int)sizeof(float);  // 96 KB
    cudaFuncSetAttribute(layer_conv_kernel,
                         cudaFuncAttributeMaxDynamicSharedMemorySize, smem_conv);

    tr_inw_kernel<<<(NL * 512 * CH * 3 + 255) / 256, 256>>>(in_w);
    tr_rsw_kernel<<<(NL * 512 * CH + 255) / 256, 256>>>(rs_w);
    tr_cw_kernel<<<(NL * 512 * 80 + 255) / 256, 256>>>(cond_w);

    start_kernel<<<(B_N * CH * T_N) / 256, 256>>>(forecast, start_w, start_b);

    dim3 grid(T_N / TT, CH / 64, B_N);
    for (int li = 0; li < NL; li++) {
        layer_conv_kernel<<<grid, 256, smem_conv>>>(context, in_b, cond_b, li, DIL[li]);
        rs_kernel<<<grid, 256>>>(rs_b, li, li == NL - 1 ? 1 : 0);
    }

    end_kernel<<<(B_N * T_N) / 256, 256>>>(forecast, end_w, end_b, out);
}

// round 3
// speedup vs baseline: 1.1438x; 1.0024x over previous
#include <cuda_runtime.h>

#define B_N 8
#define T_N 4096
#define CH  256
#define NL  8
#define TT  128
#define KC  32
#define BSW 384   // extended Bs row width for the dilated-conv kernel

typedef unsigned long long u64;

// ---- f32x2 packed helpers ----
__device__ __forceinline__ u64 bcast2(float v) {
    u64 r; unsigned int b = __float_as_uint(v);
    asm("mov.b64 %0, {%1, %1};" : "=l"(r) : "r"(b));
    return r;
}
__device__ __forceinline__ void ffma2(u64& acc, u64 a, u64 b) {
    asm("fma.rn.f32x2 %0, %1, %2, %0;" : "+l"(acc) : "l"(a), "l"(b));
}
__device__ __forceinline__ float2 unpack2(u64 v) {
    float2 f;
    asm("mov.b64 {%0, %1}, %2;" : "=f"(f.x), "=f"(f.y) : "l"(v));
    return f;
}

// ---- scratch (device globals; no allocations allowed) ----
__device__ float g_x[B_N * CH * T_N];        // 32 MB
__device__ float g_acts[B_N * CH * T_N];     // 32 MB
__device__ float g_outacc[B_N * CH * T_N];   // 32 MB
__device__ float g_inw_t[NL * 3 * CH * 512]; // [layer][k][c][o]  (o contiguous)
__device__ float g_rsw_t[NL * CH * 512];     // [layer][c][o]
__device__ float g_condw_t[NL * 80 * 512];   // [layer][m][o]

// ---------------- weight transposes (coalesced-dst layouts) ----------------
__global__ void tr_inw_kernel(const float* __restrict__ w) {
    int idx = blockIdx.x * 256 + threadIdx.x;
    if (idx >= NL * 512 * CH * 3) return;
    int k = idx % 3;
    int c = (idx / 3) % CH;
    int o = (idx / (3 * CH)) % 512;
    int i = idx / (3 * CH * 512);
    g_inw_t[((i * 3 + k) * CH + c) * 512 + o] = w[idx];
}

__global__ void tr_rsw_kernel(const float* __restrict__ w) {
    int idx = blockIdx.x * 256 + threadIdx.x;
    if (idx >= NL * 512 * CH) return;
    int c = idx & (CH - 1);
    int o = (idx >> 8) & 511;
    int i = idx >> 17;
    g_rsw_t[(i * CH + c) * 512 + o] = w[idx];
}

__global__ void tr_cw_kernel(const float* __restrict__ w) {
    int idx = blockIdx.x * 256 + threadIdx.x;
    if (idx >= NL * 512 * 80) return;
    int m = idx % 80;
    int og = idx / 80;           // global out channel 0..4095
    int i = og >> 9;
    int o = og & 511;
    g_condw_t[(i * 80 + m) * 512 + o] = w[idx];
}

// ---------------- start conv (1x1, 4->256) + zero out_acc ----------------
__global__ void start_kernel(const float* __restrict__ f,
                             const float* __restrict__ sw,
                             const float* __restrict__ sb) {
    int idx = blockIdx.x * 256 + threadIdx.x;   // over B*CH*T
    int t = idx & (T_N - 1);
    int c = (idx >> 12) & (CH - 1);
    int b = idx >> 20;
    const float* fb = f + (size_t)b * 8 * T_N;  // f0 = first 4 channels
    float acc = sb[c];
#pragma unroll
    for (int i = 0; i < 4; i++)
        acc = fmaf(fb[(size_t)i * T_N + t], sw[c * 4 + i], acc);
    g_x[idx] = acc;
    g_outacc[idx] = 0.f;
}

// ---------------- main dilated conv + cond conv + gate ----------------
// Block: (t-tile 128) x (64 j-pairs = 128 out rows) for one batch.
// Accumulators are f32x2 pairs along the output-row dimension:
//   acc2[0..1][u] = rows j0+ty*4+{0,1},{2,3}         (tanh half)
//   acc2[2..3][u] = rows 256+j0+ty*4+{0,1},{2,3}     (sigmoid half)
// cols t0 + tx + 16u, u<8.
extern __shared__ float smem_dyn[];
__global__ __launch_bounds__(256) void layer_conv_kernel(
    const float* __restrict__ context,
    const float* __restrict__ in_b,
    const float* __restrict__ cond_b,
    int li, int d) {
    float* As = smem_dyn;                 // [3][KC][128]
    float* Bs = smem_dyn + 3 * KC * 128;  // [KC][BSW]

    int tid = threadIdx.x;
    int tx = tid & 15;
    int ty = tid >> 4;
    int t0 = blockIdx.x * TT;
    int j0 = blockIdx.y * 64;
    int b  = blockIdx.z;

    const float* xb = g_x + (size_t)b * CH * T_N;
    const float* wt = g_inw_t + (size_t)li * 3 * CH * 512;

    u64 acc2[4][8];
#pragma unroll
    for (int i = 0; i < 4; i++)
#pragma unroll
        for (int u = 0; u < 8; u++) acc2[i][u] = 0ULL;

    // ===== x part: 3 dilated taps share one extended window per c-chunk =====
    for (int c0 = 0; c0 < CH; c0 += KC) {
        // As: 3*KC*128 floats -> 3072 float4, 12 per thread
#pragma unroll
        for (int e = 0; e < 12; e++) {
            int v = e * 256 + tid;
            int r4 = v & 31;
            int kkk = v >> 5;           // k*KC + kk
            int r = r4 * 4;
            int o = (r < 64) ? (j0 + r) : (256 + j0 + r - 64);
            int kk = kkk & (KC - 1);
            int k = kkk >> 5;
            float4 val = *(const float4*)(wt + ((size_t)(k * CH) + c0 + kk) * 512 + o);
            *(float4*)(As + kkk * 128 + r) = val;
        }
        // Bs: KC rows x 384 cols, window [t0-128, t0+256)
#pragma unroll
        for (int e = 0; e < 12; e++) {
            int v = e * 256 + tid;
            int c4 = v % 96;
            int kk = v / 96;
            int t = t0 - 128 + c4 * 4;
            float4 val = make_float4(0.f, 0.f, 0.f, 0.f);
            if (t >= 0 && t < T_N)
                val = *(const float4*)(xb + (size_t)(c0 + kk) * T_N + t);
            *(float4*)(Bs + kk * BSW + c4 * 4) = val;
        }
        __syncthreads();
#pragma unroll 4
        for (int kk = 0; kk < KC; kk++) {
#pragma unroll
            for (int k = 0; k < 3; k++) {
                const float* ap = As + (k * KC + kk) * 128;
                ulonglong2 A0 = *(const ulonglong2*)(ap + ty * 4);
                ulonglong2 A1 = *(const ulonglong2*)(ap + 64 + ty * 4);
                const float* bp = Bs + kk * BSW + 128 + (k - 1) * d + tx;
#pragma unroll
                for (int u = 0; u < 8; u++) {
                    u64 bv2 = bcast2(bp[u * 16]);
                    ffma2(acc2[0][u], A0.x, bv2);
                    ffma2(acc2[1][u], A0.y, bv2);
                    ffma2(acc2[2][u], A1.x, bv2);
                    ffma2(acc2[3][u], A1.y, bv2);
                }
            }
        }
        __syncthreads();
    }

    // ===== context part (1x1, K=80, zero-padded to KC chunks) =====
    const float* cwt = g_condw_t + (size_t)li * 80 * 512;
    const float* ctxb = context + (size_t)b * 80 * T_N;
    for (int m0 = 0; m0 < 80; m0 += KC) {
#pragma unroll
        for (int e = 0; e < 4; e++) {
            int v = e * 256 + tid;
            int r4 = v & 31;
            int kk = v >> 5;
            int r = r4 * 4;
            int o = (r < 64) ? (j0 + r) : (256 + j0 + r - 64);
            float4 val = make_float4(0.f, 0.f, 0.f, 0.f);
            if (m0 + kk < 80)
                val = *(const float4*)(cwt + (size_t)(m0 + kk) * 512 + o);
            *(float4*)(As + kk * 128 + r) = val;
        }
#pragma unroll
        for (int e = 0; e < 4; e++) {
            int v = e * 256 + tid;
            int c4 = v & 31;
            int kk = v >> 5;
            float4 val = make_float4(0.f, 0.f, 0.f, 0.f);
            if (m0 + kk < 80)
                val = *(const float4*)(ctxb + (size_t)(m0 + kk) * T_N + t0 + c4 * 4);
            *(float4*)(Bs + kk * BSW + 128 + c4 * 4) = val;
        }
        __syncthreads();
#pragma unroll 4
        for (int kk = 0; kk < KC; kk++) {
            const float* ap = As + kk * 128;
            ulonglong2 A0 = *(const ulonglong2*)(ap + ty * 4);
            ulonglong2 A1 = *(const ulonglong2*)(ap + 64 + ty * 4);
            const float* bp = Bs + kk * BSW + 128 + tx;
#pragma unroll
            for (int u = 0; u < 8; u++) {
                u64 bv2 = bcast2(bp[u * 16]);
                ffma2(acc2[0][u], A0.x, bv2);
                ffma2(acc2[1][u], A0.y, bv2);
                ffma2(acc2[2][u], A1.x, bv2);
                ffma2(acc2[3][u], A1.y, bv2);
            }
        }
        __syncthreads();
    }

    // ===== epilogue: biases + tanh*sigmoid gate =====
    const float* ibl = in_b + li * 512;
    const float* cbl = cond_b + li * 512;
    float* actsb = g_acts + (size_t)b * CH * T_N;
#pragma unroll
    for (int i2 = 0; i2 < 2; i2++) {
        int jj = j0 + ty * 4 + 2 * i2;     // row pair jj, jj+1
        float b1a = ibl[jj]       + cbl[jj];
        float b1b = ibl[jj + 1]   + cbl[jj + 1];
        float b2a = ibl[256 + jj]     + cbl[256 + jj];
        float b2b = ibl[256 + jj + 1] + cbl[256 + jj + 1];
        float* dst0 = actsb + (size_t)jj * T_N + t0 + tx;
        float* dst1 = dst0 + T_N;
#pragma unroll
        for (int u = 0; u < 8; u++) {
            float2 a1 = unpack2(acc2[i2][u]);
            float2 a2 = unpack2(acc2[2 + i2][u]);
            float s0 = 1.f / (1.f + __expf(-(a2.x + b2a)));
            float s1 = 1.f / (1.f + __expf(-(a2.y + b2b)));
            dst0[u * 16] = tanhf(a1.x + b1a) * s0;
            dst1[u * 16] = tanhf(a1.y + b1b) * s1;
        }
    }
}

// ---------------- res/skip 1x1 conv (256->512) + residual update ----------------
__global__ __launch_bounds__(256) void rs_kernel(const float* __restrict__ rs_b,
                                                 int li, int last) {
    __shared__ float As[KC * 128];
    __shared__ float Bs[KC * 128];

    int tid = threadIdx.x;
    int tx = tid & 15;
    int ty = tid >> 4;
    int t0 = blockIdx.x * TT;
    int j0 = blockIdx.y * 64;
    int b  = blockIdx.z;

    const float* wt = g_rsw_t + (size_t)li * CH * 512;
    const float* actsb = g_acts + (size_t)b * CH * T_N;

    u64 acc2[4][8];
#pragma unroll
    for (int i = 0; i < 4; i++)
#pragma unroll
        for (int u = 0; u < 8; u++) acc2[i][u] = 0ULL;

    for (int c0 = 0; c0 < CH; c0 += KC) {
#pragma unroll
        for (int e = 0; e < 4; e++) {
            int v = e * 256 + tid;
            int r4 = v & 31;
            int kk = v >> 5;
            int r = r4 * 4;
            int o = (r < 64) ? (j0 + r) : (256 + j0 + r - 64);
            *(float4*)(As + kk * 128 + r) =
                *(const float4*)(wt + (size_t)(c0 + kk) * 512 + o);
        }
#pragma unroll
        for (int e = 0; e < 4; e++) {
            int v = e * 256 + tid;
            int c4 = v & 31;
            int kk = v >> 5;
            *(float4*)(Bs + kk * 128 + c4 * 4) =
                *(const float4*)(actsb + (size_t)(c0 + kk) * T_N + t0 + c4 * 4);
        }
        __syncthreads();
#pragma unroll 4
        for (int kk = 0; kk < KC; kk++) {
            const float* ap = As + kk * 128;
            ulonglong2 A0 = *(const ulonglong2*)(ap + ty * 4);
            ulonglong2 A1 = *(const ulonglong2*)(ap + 64 + ty * 4);
            const float* bp = Bs + kk * 128 + tx;
#pragma unroll
            for (int u = 0; u < 8; u++) {
                u64 bv2 = bcast2(bp[u * 16]);
                ffma2(acc2[0][u], A0.x, bv2);
                ffma2(acc2[1][u], A0.y, bv2);
                ffma2(acc2[2][u], A1.x, bv2);
                ffma2(acc2[3][u], A1.y, bv2);
            }
        }
        __syncthreads();
    }

    const float* rbl = rs_b + li * 512;
    size_t base = (size_t)b * CH * T_N;
#pragma unroll
    for (int i2 = 0; i2 < 2; i2++) {
        int jj = j0 + ty * 4 + 2 * i2;     // row pair jj, jj+1
        float rb1a = rbl[jj];
        float rb1b = rbl[jj + 1];
        float rb2a = rbl[256 + jj];
        float rb2b = rbl[256 + jj + 1];
        size_t idx0 = base + (size_t)jj * T_N + t0 + tx;
        size_t idx1 = idx0 + T_N;
#pragma unroll
        for (int u = 0; u < 8; u++) {
            float2 r1 = unpack2(acc2[i2][u]);
            float2 r2 = unpack2(acc2[2 + i2][u]);
            size_t o = (size_t)u * 16;
            if (!last) {
                g_x[idx0 + o] += r1.x + rb1a;
                g_x[idx1 + o] += r1.y + rb1b;
                g_outacc[idx0 + o] += r2.x + rb2a;
                g_outacc[idx1 + o] += r2.y + rb2b;
            } else {
                g_outacc[idx0 + o] += r1.x + rb1a;   // last layer: output += rs[:256]
                g_outacc[idx1 + o] += r1.y + rb1b;
            }
        }
    }
}

// ---------------- end conv (1x1, 256->8) + affine transform ----------------
__global__ void end_kernel(const float* __restrict__ forecast,
                           const float* __restrict__ ew,
                           const float* __restrict__ eb,
                           float* __restrict__ out) {
    __shared__ float w[8 * CH];
    int tid = threadIdx.x;
    for (int e = tid; e < 8 * CH; e += 256) w[e] = ew[e];
    __syncthreads();

    int idx = blockIdx.x * 256 + tid;  // over B*T
    int t = idx & (T_N - 1);
    int b = idx >> 12;

    float acc[8];
#pragma unroll
    for (int o = 0; o < 8; o++) acc[o] = eb[o];
    const float* oa = g_outacc + (size_t)b * CH * T_N + t;
    for (int c = 0; c < CH; c++) {
        float v = oa[(size_t)c * T_N];
#pragma unroll
        for (int o = 0; o < 8; o++)
            acc[o] = fmaf(v, w[o * CH + c], acc[o]);
    }

    const float* fb = forecast + (size_t)b * 8 * T_N + t;
    float* cc = out + (size_t)b * 8 * T_N + t;                       // concat [B,8,T]
    float* lo = out + (size_t)B_N * 8 * T_N + (size_t)b * 4 * T_N + t; // log_s [B,4,T]
#pragma unroll
    for (int l = 0; l < 4; l++) {
        cc[(size_t)l * T_N] = fb[(size_t)l * T_N];                   // f0 passthrough
        float ls = acc[4 + l];                                       // log_s channel
        cc[(size_t)(4 + l) * T_N] =
            expf(ls) * fb[(size_t)(4 + l) * T_N] + acc[l];           // exp(ls)*f1 + b
        lo[(size_t)l * T_N] = ls;
    }
}

// ---------------- launch ----------------
static const int DIL[NL] = {1, 2, 4, 8, 16, 32, 64, 128};

extern "C" void kernel_launch(void* const* d_in, const int* in_sizes, int n_in,
                              void* d_out, int out_size) {
    const float* forecast = (const float*)d_in[0];
    const float* context  = (const float*)d_in[1];
    const float* start_w  = (const float*)d_in[2];
    const float* start_b  = (const float*)d_in[3];
    const float* cond_w   = (const float*)d_in[4];
    const float* cond_b   = (const float*)d_in[5];
    const float* in_w     = (const float*)d_in[6];
    const float* in_b     = (const float*)d_in[7];
    const float* rs_w     = (const float*)d_in[8];
    const float* rs_b     = (const float*)d_in[9];
    const float* end_w    = (const float*)d_in[10];
    const float* end_b    = (const float*)d_in[11];
    float* out = (float*)d_out;
    (void)in_sizes; (void)n_in; (void)out_size;

    int smem_conv = (3 * KC * 128 + KC * BSW) * (int)sizeof(float);  // 96 KB
    cudaFuncSetAttribute(layer_conv_kernel,
                         cudaFuncAttributeMaxDynamicSharedMemorySize, smem_conv);

    tr_inw_kernel<<<(NL * 512 * CH * 3 + 255) / 256, 256>>>(in_w);
    tr_rsw_kernel<<<(NL * 512 * CH + 255) / 256, 256>>>(rs_w);
    tr_cw_kernel<<<(NL * 512 * 80 + 255) / 256, 256>>>(cond_w);

    start_kernel<<<(B_N * CH * T_N) / 256, 256>>>(forecast, start_w, start_b);

    dim3 grid(T_N / TT, CH / 64, B_N);
    for (int li = 0; li < NL; li++) {
        layer_conv_kernel<<<grid, 256, smem_conv>>>(context, in_b, cond_b, li, DIL[li]);
        rs_kernel<<<grid, 256>>>(rs_b, li, li == NL - 1 ? 1 : 0);
    }

    end_kernel<<<(B_N * T_N) / 256, 256>>>(forecast, end_w, end_b, out);
}